// round 1
// baseline (speedup 1.0000x reference)
#include <cuda_runtime.h>
#include <cmath>

// Problem constants
#define BATCH 8
#define CHN 3
#define IMG 224
#define HP 112      // Hp = Wp = 112
#define FIN 12      // patch features
#define D 128       // hidden per direction
#define L 112       // scan length (both stages)
#define NSEQ 896    // Hp*B = Wp*B
#define M_TOT (L * NSEQ)   // 100352

// Scratch (device globals — no dynamic allocation allowed)
__device__ float g_a2[(size_t)M_TOT * 256];   // stage-1 output == stage-2 input, layout [hp][wp*8+b][ch]
__device__ float g_u2[(size_t)M_TOT * 768];   // stage-2 GEMM output, layout [l*896+n][ch*3+j]

__device__ __forceinline__ float sigmoidf_(float v) {
    return 1.0f / (1.0f + __expf(-v));
}

// ---------------------------------------------------------------------------
// Kernel 1: fused patch-extract + (x @ W1) + bidirectional SRU scan (k=4)
// grid (896, 2), block 128. blockIdx.x = n1 = hp*8+b, blockIdx.y = dir,
// threadIdx.x = d (channel). Writes h1 directly in stage-2 input layout.
// ---------------------------------------------------------------------------
__global__ void __launch_bounds__(128) k1_scan1(
    const float* __restrict__ x, const float* __restrict__ W1,
    const float* __restrict__ wc1, const float* __restrict__ b1)
{
    const int n1  = blockIdx.x;        // hp*8 + b
    const int dir = blockIdx.y;
    const int d   = threadIdx.x;       // 0..127
    const int hp  = n1 >> 3;
    const int b   = n1 & 7;

    // W1 columns for this output channel: col = (dir*128+d)*4 + j, j=0..3
    float w[FIN][4];
    const int col0 = (dir * D + d) * 4;
#pragma unroll
    for (int f = 0; f < FIN; f++) {
#pragma unroll
        for (int j = 0; j < 4; j++)
            w[f][j] = W1[f * 1024 + col0 + j];
    }
    const int chg = dir * D + d;
    const float vf = wc1[chg];
    const float vr = wc1[256 + chg];
    const float bf = b1[chg];
    const float br = b1[256 + chg];

    __shared__ float sp[2][FIN];

    const int l0 = dir ? (L - 1) : 0;
    const int dl = dir ? -1 : 1;

    // patch element for f = c*4 + wh*2 + ww at column l:
    //   x[((b*3+c)*224 + 2*hp + wh)*224 + 2*l + ww]
    int xrowbase = 0, xww = 0;
    if (d < FIN) {
        int c  = d >> 2;
        int wh = (d >> 1) & 1;
        xww    = d & 1;
        xrowbase = ((b * 3 + c) * IMG + 2 * hp + wh) * IMG;
        sp[0][d] = x[xrowbase + 2 * l0 + xww];
    }
    __syncthreads();

    float cst = 0.0f;
    for (int s = 0; s < L; s++) {
        const int l   = l0 + dl * s;
        const int cur = s & 1;
        if (d < FIN && (s + 1) < L) {
            sp[cur ^ 1][d] = x[xrowbase + 2 * (l + dl) + xww];
        }
        float u0 = 0.f, u1 = 0.f, u2 = 0.f, u3 = 0.f;
#pragma unroll
        for (int f = 0; f < FIN; f++) {
            const float p = sp[cur][f];
            u0 = fmaf(p, w[f][0], u0);
            u1 = fmaf(p, w[f][1], u1);
            u2 = fmaf(p, w[f][2], u2);
            u3 = fmaf(p, w[f][3], u3);
        }
        const float fg = sigmoidf_(u1 + vf * cst + bf);
        cst = fg * (cst - u0) + u0;
        const float rg = sigmoidf_(u2 + vr * cst + br);
        const float h  = rg * (cst - u3) + u3;
        // stage-2 layout: a2[hp][wp*8+b][ch], wp = l
        g_a2[((size_t)hp * NSEQ + l * 8 + b) * 256 + chg] = h;
        __syncthreads();
    }
}

// ---------------------------------------------------------------------------
// Kernel 2: fp32 GEMM  U2[M=100352, 768] = a2[M, 256] @ W2[256, 768]
// Tiles: BM=128, BN=64, BK=16; 256 threads; 8x4 per-thread microtile.
// M = 784*128, N = 12*64, K = 16*16 -> no bounds checks needed.
// ---------------------------------------------------------------------------
__global__ void __launch_bounds__(256) k2_gemm(const float* __restrict__ W2)
{
    __shared__ float As[16][132];  // [k][m], padded
    __shared__ float Bs[16][68];   // [k][n], padded

    const int tid = threadIdx.x;
    const int tx  = tid & 15;      // n group
    const int ty  = tid >> 4;      // m group
    const int m0  = blockIdx.x * 128;
    const int n0  = blockIdx.y * 64;

    const float* A = g_a2;
    float acc[8][4];
#pragma unroll
    for (int i = 0; i < 8; i++)
#pragma unroll
        for (int j = 0; j < 4; j++) acc[i][j] = 0.f;

    for (int k0 = 0; k0 < 256; k0 += 16) {
        // load A tile (128x16), transposed into As[k][m]
#pragma unroll
        for (int q = 0; q < 2; q++) {
            const int v   = tid * 2 + q;
            const int row = v >> 2;
            const int kq  = (v & 3) * 4;
            const float4 av = *(const float4*)(A + (size_t)(m0 + row) * 256 + k0 + kq);
            As[kq + 0][row] = av.x;
            As[kq + 1][row] = av.y;
            As[kq + 2][row] = av.z;
            As[kq + 3][row] = av.w;
        }
        // load B tile (16x64)
        {
            const int kk = tid >> 4;
            const int n4 = (tid & 15) * 4;
            const float4 bv = *(const float4*)(W2 + (size_t)(k0 + kk) * 768 + n0 + n4);
            *(float4*)&Bs[kk][n4] = bv;
        }
        __syncthreads();
#pragma unroll
        for (int kk = 0; kk < 16; kk++) {
            float a[8], bb[4];
#pragma unroll
            for (int i = 0; i < 8; i++) a[i] = As[kk][ty * 8 + i];
#pragma unroll
            for (int j = 0; j < 4; j++) bb[j] = Bs[kk][tx * 4 + j];
#pragma unroll
            for (int i = 0; i < 8; i++)
#pragma unroll
                for (int j = 0; j < 4; j++)
                    acc[i][j] = fmaf(a[i], bb[j], acc[i][j]);
        }
        __syncthreads();
    }

#pragma unroll
    for (int i = 0; i < 8; i++) {
        float4 o;
        o.x = acc[i][0]; o.y = acc[i][1]; o.z = acc[i][2]; o.w = acc[i][3];
        *(float4*)(g_u2 + (size_t)(m0 + ty * 8 + i) * 768 + n0 + tx * 4) = o;
    }
}

// ---------------------------------------------------------------------------
// Kernel 3: bidirectional SRU scan (k=3, xprime = a2 * sqrt(2)) + output permute
// grid (896, 2), block 128. blockIdx.x = n2 = wp*8+b, dir = blockIdx.y,
// thread d = channel. Writes out[b][ch][hp][wp].
// ---------------------------------------------------------------------------
__global__ void __launch_bounds__(128) k3_scan2(
    const float* __restrict__ wc2, const float* __restrict__ b2,
    float* __restrict__ out)
{
    const int n2  = blockIdx.x;      // wp*8 + b
    const int dir = blockIdx.y;
    const int d   = threadIdx.x;
    const int wp  = n2 >> 3;
    const int b   = n2 & 7;
    const int ch  = dir * D + d;

    const float vf = wc2[ch];
    const float vr = wc2[256 + ch];
    const float bf = b2[ch];
    const float br = b2[256 + ch];
    const float SC = 1.41421356237309515f;  // sqrt(2), rescale for k=3

    const int l0 = dir ? (L - 1) : 0;
    const int dl = dir ? -1 : 1;

    float cst = 0.0f;
    for (int s = 0; s < L; s++) {
        const int l = l0 + dl * s;
        const size_t base = (size_t)l * NSEQ + n2;
        const float* up = g_u2 + base * 768 + (size_t)ch * 3;
        const float u0  = up[0];
        const float u1  = up[1];
        const float u2v = up[2];
        const float xp  = g_a2[base * 256 + ch] * SC;
        const float fg  = sigmoidf_(u1 + vf * cst + bf);
        cst = fg * (cst - u0) + u0;
        const float rg = sigmoidf_(u2v + vr * cst + br);
        const float h  = rg * (cst - xp) + xp;
        // out[b][ch][hp=l][wp]
        out[((size_t)(b * 256 + ch) * HP + l) * HP + wp] = h;
    }
}

// ---------------------------------------------------------------------------
extern "C" void kernel_launch(void* const* d_in, const int* in_sizes, int n_in,
                              void* d_out, int out_size)
{
    const float* x   = (const float*)d_in[0];
    const float* W1  = (const float*)d_in[1];
    const float* wc1 = (const float*)d_in[2];
    const float* b1  = (const float*)d_in[3];
    const float* W2  = (const float*)d_in[4];
    const float* wc2 = (const float*)d_in[5];
    const float* b2  = (const float*)d_in[6];
    float* out = (float*)d_out;

    k1_scan1<<<dim3(NSEQ, 2), 128>>>(x, W1, wc1, b1);
    k2_gemm<<<dim3(M_TOT / 128, 768 / 64), 256>>>(W2);
    k3_scan2<<<dim3(NSEQ, 2), 128>>>(wc2, b2, out);
}

// round 2
// speedup vs baseline: 1.8622x; 1.8622x over previous
#include <cuda_runtime.h>
#include <cmath>

// Problem constants
#define BATCH 8
#define CHN 3
#define IMG 224
#define HP 112      // Hp = Wp = 112
#define FIN 12      // patch features
#define D 128       // hidden per direction
#define L 112       // scan length (both stages)
#define NSEQ 896    // Hp*B = Wp*B
#define M_TOT (L * NSEQ)   // 100352

// Scratch (device globals — no dynamic allocation allowed)
__device__ float g_a2[(size_t)M_TOT * 256];   // stage-1 output == stage-2 input, layout [hp][wp*8+b][ch]
__device__ float g_u2[(size_t)M_TOT * 768];   // stage-2 GEMM output, layout [l*896+n][ch*3+j]

__device__ __forceinline__ float sigmoidf_(float v) {
    return 1.0f / (1.0f + __expf(-v));
}

__device__ __forceinline__ unsigned f2tf32(float v) {
    unsigned r;
    asm("cvt.rna.tf32.f32 %0, %1;" : "=r"(r) : "f"(v));
    return r;
}

// ---------------------------------------------------------------------------
// Kernel 1: fused patch-extract + (x @ W1) + bidirectional SRU scan (k=4)
// ---------------------------------------------------------------------------
__global__ void __launch_bounds__(128) k1_scan1(
    const float* __restrict__ x, const float* __restrict__ W1,
    const float* __restrict__ wc1, const float* __restrict__ b1)
{
    const int n1  = blockIdx.x;        // hp*8 + b
    const int dir = blockIdx.y;
    const int d   = threadIdx.x;       // 0..127
    const int hp  = n1 >> 3;
    const int b   = n1 & 7;

    float w[FIN][4];
    const int col0 = (dir * D + d) * 4;
#pragma unroll
    for (int f = 0; f < FIN; f++) {
#pragma unroll
        for (int j = 0; j < 4; j++)
            w[f][j] = W1[f * 1024 + col0 + j];
    }
    const int chg = dir * D + d;
    const float vf = wc1[chg];
    const float vr = wc1[256 + chg];
    const float bf = b1[chg];
    const float br = b1[256 + chg];

    __shared__ float sp[2][FIN];

    const int l0 = dir ? (L - 1) : 0;
    const int dl = dir ? -1 : 1;

    int xrowbase = 0, xww = 0;
    if (d < FIN) {
        int c  = d >> 2;
        int wh = (d >> 1) & 1;
        xww    = d & 1;
        xrowbase = ((b * 3 + c) * IMG + 2 * hp + wh) * IMG;
        sp[0][d] = x[xrowbase + 2 * l0 + xww];
    }
    __syncthreads();

    float cst = 0.0f;
    for (int s = 0; s < L; s++) {
        const int l   = l0 + dl * s;
        const int cur = s & 1;
        if (d < FIN && (s + 1) < L) {
            sp[cur ^ 1][d] = x[xrowbase + 2 * (l + dl) + xww];
        }
        float u0 = 0.f, u1 = 0.f, u2 = 0.f, u3 = 0.f;
#pragma unroll
        for (int f = 0; f < FIN; f++) {
            const float p = sp[cur][f];
            u0 = fmaf(p, w[f][0], u0);
            u1 = fmaf(p, w[f][1], u1);
            u2 = fmaf(p, w[f][2], u2);
            u3 = fmaf(p, w[f][3], u3);
        }
        const float fg = sigmoidf_(u1 + vf * cst + bf);
        cst = fg * (cst - u0) + u0;
        const float rg = sigmoidf_(u2 + vr * cst + br);
        const float h  = rg * (cst - u3) + u3;
        g_a2[((size_t)hp * NSEQ + l * 8 + b) * 256 + chg] = h;
        __syncthreads();
    }
}

// ---------------------------------------------------------------------------
// Kernel 2: tf32 tensor-core GEMM  U2[100352,768] = a2[100352,256] @ W2[256,768]
// BM=128, BN=128, BK=16; 256 threads (8 warps, 4x2); warp tile 32x64;
// mma.sync.m16n8k8.tf32, double-buffered smem, 136-float stride (bank-clean).
// grid = (N/128=6, M/128=784): n varies fastest -> A m-row tiles hit L2.
// ---------------------------------------------------------------------------
#define SA 136
__global__ void __launch_bounds__(256, 2) k2_gemm_tf32(const float* __restrict__ W2)
{
    __shared__ unsigned As[2][16 * SA];
    __shared__ unsigned Bs[2][16 * SA];

    const int tid  = threadIdx.x;
    const int lane = tid & 31;
    const int gid  = lane >> 2;     // 0..7
    const int tig  = lane & 3;      // 0..3
    const int warp = tid >> 5;
    const int wm   = (warp & 3) * 32;   // warp m offset
    const int wn   = (warp >> 2) * 64;  // warp n offset
    const int n0   = blockIdx.x * 128;
    const int m0   = blockIdx.y * 128;

    const float* A = g_a2;

    // load index precompute
    const int ar0 = tid >> 2;           // 0..63
    const int ak0 = (tid & 3) * 4;
    const int ar1 = ar0 + 64;
    const int br0 = tid >> 5;           // 0..7
    const int bc0 = (tid & 31) * 4;
    const int br1 = br0 + 8;

    float4 ra0, ra1, rb0, rb1;

    // prologue: tile 0
    ra0 = *(const float4*)(A + (size_t)(m0 + ar0) * 256 + ak0);
    ra1 = *(const float4*)(A + (size_t)(m0 + ar1) * 256 + ak0);
    rb0 = *(const float4*)(W2 + (size_t)br0 * 768 + n0 + bc0);
    rb1 = *(const float4*)(W2 + (size_t)br1 * 768 + n0 + bc0);

    {
        unsigned* as = As[0];
        as[(ak0 + 0) * SA + ar0] = f2tf32(ra0.x);
        as[(ak0 + 1) * SA + ar0] = f2tf32(ra0.y);
        as[(ak0 + 2) * SA + ar0] = f2tf32(ra0.z);
        as[(ak0 + 3) * SA + ar0] = f2tf32(ra0.w);
        as[(ak0 + 0) * SA + ar1] = f2tf32(ra1.x);
        as[(ak0 + 1) * SA + ar1] = f2tf32(ra1.y);
        as[(ak0 + 2) * SA + ar1] = f2tf32(ra1.z);
        as[(ak0 + 3) * SA + ar1] = f2tf32(ra1.w);
        uint4 b0 = make_uint4(f2tf32(rb0.x), f2tf32(rb0.y), f2tf32(rb0.z), f2tf32(rb0.w));
        uint4 b1 = make_uint4(f2tf32(rb1.x), f2tf32(rb1.y), f2tf32(rb1.z), f2tf32(rb1.w));
        *(uint4*)&Bs[0][br0 * SA + bc0] = b0;
        *(uint4*)&Bs[0][br1 * SA + bc0] = b1;
    }
    __syncthreads();

    float c[2][8][4];
#pragma unroll
    for (int mi = 0; mi < 2; mi++)
#pragma unroll
        for (int ni = 0; ni < 8; ni++)
#pragma unroll
            for (int j = 0; j < 4; j++) c[mi][ni][j] = 0.f;

    for (int kt = 0; kt < 16; kt++) {
        const int buf = kt & 1;
        if (kt < 15) {
            const int k0 = (kt + 1) * 16;
            ra0 = *(const float4*)(A + (size_t)(m0 + ar0) * 256 + k0 + ak0);
            ra1 = *(const float4*)(A + (size_t)(m0 + ar1) * 256 + k0 + ak0);
            rb0 = *(const float4*)(W2 + (size_t)(k0 + br0) * 768 + n0 + bc0);
            rb1 = *(const float4*)(W2 + (size_t)(k0 + br1) * 768 + n0 + bc0);
        }

        const unsigned* as = As[buf];
        const unsigned* bs = Bs[buf];
#pragma unroll
        for (int ks = 0; ks < 16; ks += 8) {
            unsigned a[2][4];
#pragma unroll
            for (int mi = 0; mi < 2; mi++) {
                const int mb = wm + mi * 16 + gid;
                a[mi][0] = as[(ks + tig) * SA + mb];
                a[mi][1] = as[(ks + tig) * SA + mb + 8];
                a[mi][2] = as[(ks + tig + 4) * SA + mb];
                a[mi][3] = as[(ks + tig + 4) * SA + mb + 8];
            }
#pragma unroll
            for (int ni = 0; ni < 8; ni++) {
                const int nb = wn + ni * 8 + gid;
                const unsigned b0 = bs[(ks + tig) * SA + nb];
                const unsigned b1 = bs[(ks + tig + 4) * SA + nb];
#pragma unroll
                for (int mi = 0; mi < 2; mi++) {
                    asm volatile(
                        "mma.sync.aligned.m16n8k8.row.col.f32.tf32.tf32.f32 "
                        "{%0,%1,%2,%3}, {%4,%5,%6,%7}, {%8,%9}, {%0,%1,%2,%3};"
                        : "+f"(c[mi][ni][0]), "+f"(c[mi][ni][1]),
                          "+f"(c[mi][ni][2]), "+f"(c[mi][ni][3])
                        : "r"(a[mi][0]), "r"(a[mi][1]), "r"(a[mi][2]), "r"(a[mi][3]),
                          "r"(b0), "r"(b1));
                }
            }
        }

        if (kt < 15) {
            const int nb = buf ^ 1;
            unsigned* asn = As[nb];
            asn[(ak0 + 0) * SA + ar0] = f2tf32(ra0.x);
            asn[(ak0 + 1) * SA + ar0] = f2tf32(ra0.y);
            asn[(ak0 + 2) * SA + ar0] = f2tf32(ra0.z);
            asn[(ak0 + 3) * SA + ar0] = f2tf32(ra0.w);
            asn[(ak0 + 0) * SA + ar1] = f2tf32(ra1.x);
            asn[(ak0 + 1) * SA + ar1] = f2tf32(ra1.y);
            asn[(ak0 + 2) * SA + ar1] = f2tf32(ra1.z);
            asn[(ak0 + 3) * SA + ar1] = f2tf32(ra1.w);
            uint4 b0 = make_uint4(f2tf32(rb0.x), f2tf32(rb0.y), f2tf32(rb0.z), f2tf32(rb0.w));
            uint4 b1 = make_uint4(f2tf32(rb1.x), f2tf32(rb1.y), f2tf32(rb1.z), f2tf32(rb1.w));
            *(uint4*)&Bs[nb][br0 * SA + bc0] = b0;
            *(uint4*)&Bs[nb][br1 * SA + bc0] = b1;
            __syncthreads();
        }
    }

    // epilogue: write C
#pragma unroll
    for (int mi = 0; mi < 2; mi++) {
#pragma unroll
        for (int ni = 0; ni < 8; ni++) {
            const int r0  = m0 + wm + mi * 16 + gid;
            const int col = n0 + wn + ni * 8 + tig * 2;
            *(float2*)(g_u2 + (size_t)r0 * 768 + col)      = make_float2(c[mi][ni][0], c[mi][ni][1]);
            *(float2*)(g_u2 + (size_t)(r0 + 8) * 768 + col) = make_float2(c[mi][ni][2], c[mi][ni][3]);
        }
    }
}

// ---------------------------------------------------------------------------
// Kernel 3: bidirectional SRU scan (k=3, xprime = a2 * sqrt(2)) + output permute
// ---------------------------------------------------------------------------
__global__ void __launch_bounds__(128) k3_scan2(
    const float* __restrict__ wc2, const float* __restrict__ b2,
    float* __restrict__ out)
{
    const int n2  = blockIdx.x;      // wp*8 + b
    const int dir = blockIdx.y;
    const int d   = threadIdx.x;
    const int wp  = n2 >> 3;
    const int b   = n2 & 7;
    const int ch  = dir * D + d;

    const float vf = wc2[ch];
    const float vr = wc2[256 + ch];
    const float bf = b2[ch];
    const float br = b2[256 + ch];
    const float SC = 1.41421356237309515f;  // sqrt(2), rescale for k=3

    const int l0 = dir ? (L - 1) : 0;
    const int dl = dir ? -1 : 1;

    float cst = 0.0f;
    for (int s = 0; s < L; s++) {
        const int l = l0 + dl * s;
        const size_t base = (size_t)l * NSEQ + n2;
        const float* up = g_u2 + base * 768 + (size_t)ch * 3;
        const float u0  = up[0];
        const float u1  = up[1];
        const float u2v = up[2];
        const float xp  = g_a2[base * 256 + ch] * SC;
        const float fg  = sigmoidf_(u1 + vf * cst + bf);
        cst = fg * (cst - u0) + u0;
        const float rg = sigmoidf_(u2v + vr * cst + br);
        const float h  = rg * (cst - xp) + xp;
        out[((size_t)(b * 256 + ch) * HP + l) * HP + wp] = h;
    }
}

// ---------------------------------------------------------------------------
extern "C" void kernel_launch(void* const* d_in, const int* in_sizes, int n_in,
                              void* d_out, int out_size)
{
    const float* x   = (const float*)d_in[0];
    const float* W1  = (const float*)d_in[1];
    const float* wc1 = (const float*)d_in[2];
    const float* b1  = (const float*)d_in[3];
    const float* W2  = (const float*)d_in[4];
    const float* wc2 = (const float*)d_in[5];
    const float* b2  = (const float*)d_in[6];
    float* out = (float*)d_out;

    k1_scan1<<<dim3(NSEQ, 2), 128>>>(x, W1, wc1, b1);
    k2_gemm_tf32<<<dim3(768 / 128, M_TOT / 128), 256>>>(W2);
    k3_scan2<<<dim3(NSEQ, 2), 128>>>(wc2, b2, out);
}

// round 3
// speedup vs baseline: 2.3139x; 1.2425x over previous
#include <cuda_runtime.h>
#include <cmath>

// Problem constants
#define BATCH 8
#define CHN 3
#define IMG 224
#define HP 112      // Hp = Wp = 112
#define FIN 12      // patch features
#define D 128       // hidden per direction
#define L 112       // scan length (both stages)
#define NSEQ 896    // Hp*B = Wp*B
#define M_TOT (L * NSEQ)   // 100352

// Scratch (device globals — no dynamic allocation allowed)
__device__ float g_a2[(size_t)M_TOT * 256];   // layout [hp][wp*8+b][ch]
__device__ float g_u2[(size_t)M_TOT * 768];   // layout [l*896+n][ch*3+j]

__device__ __forceinline__ float sigmoidf_(float v) {
    return 1.0f / (1.0f + __expf(-v));
}

__device__ __forceinline__ unsigned f2tf32(float v) {
    unsigned r;
    asm("cvt.rna.tf32.f32 %0, %1;" : "=r"(r) : "f"(v));
    return r;
}

// ---------------------------------------------------------------------------
// Kernel 1: fused patch-extract + (x @ W1) + bidirectional SRU scan (k=4)
// Warp-autonomous: patch values broadcast via shfl (no smem, no barriers).
// ---------------------------------------------------------------------------
__global__ void __launch_bounds__(128) k1_scan1(
    const float* __restrict__ x, const float* __restrict__ W1,
    const float* __restrict__ wc1, const float* __restrict__ b1)
{
    const int n1  = blockIdx.x;        // hp*8 + b
    const int dir = blockIdx.y;
    const int d   = threadIdx.x;       // 0..127 (output channel)
    const int lid = d & 31;
    const int hp  = n1 >> 3;
    const int b   = n1 & 7;

    float w[FIN][4];
    const int col0 = (dir * D + d) * 4;
#pragma unroll
    for (int f = 0; f < FIN; f++) {
#pragma unroll
        for (int j = 0; j < 4; j++)
            w[f][j] = W1[f * 1024 + col0 + j];
    }
    const int chg = dir * D + d;
    const float vf = wc1[chg];
    const float vr = wc1[256 + chg];
    const float bf = b1[chg];
    const float br = b1[256 + chg];

    const int l0 = dir ? (L - 1) : 0;
    const int dl = dir ? -1 : 1;

    // Each warp: lanes 0..11 own one patch element (c, wh, ww)
    int xrowbase = 0, xww = 0;
    float nv = 0.0f;
    if (lid < FIN) {
        int c  = lid >> 2;
        int wh = (lid >> 1) & 1;
        xww    = lid & 1;
        xrowbase = ((b * 3 + c) * IMG + 2 * hp + wh) * IMG;
        nv = x[xrowbase + 2 * l0 + xww];
    }

    float* outp = g_a2 + ((size_t)hp * NSEQ + l0 * 8 + b) * 256 + chg;
    const ptrdiff_t ostep = (ptrdiff_t)dl * 8 * 256;

    float cst = 0.0f;
    for (int s = 0; s < L; s++) {
        const float cv = nv;
        if (lid < FIN && (s + 1) < L) {
            nv = x[xrowbase + 2 * (l0 + dl * (s + 1)) + xww];
        }
        float u0 = 0.f, u1 = 0.f, u2 = 0.f, u3 = 0.f;
#pragma unroll
        for (int f = 0; f < FIN; f++) {
            const float p = __shfl_sync(0xffffffffu, cv, f);
            u0 = fmaf(p, w[f][0], u0);
            u1 = fmaf(p, w[f][1], u1);
            u2 = fmaf(p, w[f][2], u2);
            u3 = fmaf(p, w[f][3], u3);
        }
        const float fg = sigmoidf_(u1 + vf * cst + bf);
        cst = fg * (cst - u0) + u0;
        const float rg = sigmoidf_(u2 + vr * cst + br);
        const float h  = rg * (cst - u3) + u3;
        *outp = h;
        outp += ostep;
    }
}

// ---------------------------------------------------------------------------
// Kernel 2: tf32 tensor-core GEMM  U2[100352,768] = a2[100352,256] @ W2[256,768]
// BM=128, BN=128, BK=16; 256 threads; warp tile 32x64; mma.m16n8k8.tf32.
// ---------------------------------------------------------------------------
#define SA 136
__global__ void __launch_bounds__(256, 2) k2_gemm_tf32(const float* __restrict__ W2)
{
    __shared__ unsigned As[2][16 * SA];
    __shared__ unsigned Bs[2][16 * SA];

    const int tid  = threadIdx.x;
    const int lane = tid & 31;
    const int gid  = lane >> 2;     // 0..7
    const int tig  = lane & 3;      // 0..3
    const int warp = tid >> 5;
    const int wm   = (warp & 3) * 32;   // warp m offset
    const int wn   = (warp >> 2) * 64;  // warp n offset
    const int n0   = blockIdx.x * 128;
    const int m0   = blockIdx.y * 128;

    const float* A = g_a2;

    const int ar0 = tid >> 2;           // 0..63
    const int ak0 = (tid & 3) * 4;
    const int ar1 = ar0 + 64;
    const int br0 = tid >> 5;           // 0..7
    const int bc0 = (tid & 31) * 4;
    const int br1 = br0 + 8;

    float4 ra0, ra1, rb0, rb1;

    ra0 = *(const float4*)(A + (size_t)(m0 + ar0) * 256 + ak0);
    ra1 = *(const float4*)(A + (size_t)(m0 + ar1) * 256 + ak0);
    rb0 = *(const float4*)(W2 + (size_t)br0 * 768 + n0 + bc0);
    rb1 = *(const float4*)(W2 + (size_t)br1 * 768 + n0 + bc0);

    {
        unsigned* as = As[0];
        as[(ak0 + 0) * SA + ar0] = f2tf32(ra0.x);
        as[(ak0 + 1) * SA + ar0] = f2tf32(ra0.y);
        as[(ak0 + 2) * SA + ar0] = f2tf32(ra0.z);
        as[(ak0 + 3) * SA + ar0] = f2tf32(ra0.w);
        as[(ak0 + 0) * SA + ar1] = f2tf32(ra1.x);
        as[(ak0 + 1) * SA + ar1] = f2tf32(ra1.y);
        as[(ak0 + 2) * SA + ar1] = f2tf32(ra1.z);
        as[(ak0 + 3) * SA + ar1] = f2tf32(ra1.w);
        uint4 b0 = make_uint4(f2tf32(rb0.x), f2tf32(rb0.y), f2tf32(rb0.z), f2tf32(rb0.w));
        uint4 b1 = make_uint4(f2tf32(rb1.x), f2tf32(rb1.y), f2tf32(rb1.z), f2tf32(rb1.w));
        *(uint4*)&Bs[0][br0 * SA + bc0] = b0;
        *(uint4*)&Bs[0][br1 * SA + bc0] = b1;
    }
    __syncthreads();

    float c[2][8][4];
#pragma unroll
    for (int mi = 0; mi < 2; mi++)
#pragma unroll
        for (int ni = 0; ni < 8; ni++)
#pragma unroll
            for (int j = 0; j < 4; j++) c[mi][ni][j] = 0.f;

    for (int kt = 0; kt < 16; kt++) {
        const int buf = kt & 1;
        if (kt < 15) {
            const int k0 = (kt + 1) * 16;
            ra0 = *(const float4*)(A + (size_t)(m0 + ar0) * 256 + k0 + ak0);
            ra1 = *(const float4*)(A + (size_t)(m0 + ar1) * 256 + k0 + ak0);
            rb0 = *(const float4*)(W2 + (size_t)(k0 + br0) * 768 + n0 + bc0);
            rb1 = *(const float4*)(W2 + (size_t)(k0 + br1) * 768 + n0 + bc0);
        }

        const unsigned* as = As[buf];
        const unsigned* bs = Bs[buf];
#pragma unroll
        for (int ks = 0; ks < 16; ks += 8) {
            unsigned a[2][4];
#pragma unroll
            for (int mi = 0; mi < 2; mi++) {
                const int mb = wm + mi * 16 + gid;
                a[mi][0] = as[(ks + tig) * SA + mb];
                a[mi][1] = as[(ks + tig) * SA + mb + 8];
                a[mi][2] = as[(ks + tig + 4) * SA + mb];
                a[mi][3] = as[(ks + tig + 4) * SA + mb + 8];
            }
#pragma unroll
            for (int ni = 0; ni < 8; ni++) {
                const int nb = wn + ni * 8 + gid;
                const unsigned b0 = bs[(ks + tig) * SA + nb];
                const unsigned b1 = bs[(ks + tig + 4) * SA + nb];
#pragma unroll
                for (int mi = 0; mi < 2; mi++) {
                    asm volatile(
                        "mma.sync.aligned.m16n8k8.row.col.f32.tf32.tf32.f32 "
                        "{%0,%1,%2,%3}, {%4,%5,%6,%7}, {%8,%9}, {%0,%1,%2,%3};"
                        : "+f"(c[mi][ni][0]), "+f"(c[mi][ni][1]),
                          "+f"(c[mi][ni][2]), "+f"(c[mi][ni][3])
                        : "r"(a[mi][0]), "r"(a[mi][1]), "r"(a[mi][2]), "r"(a[mi][3]),
                          "r"(b0), "r"(b1));
                }
            }
        }

        if (kt < 15) {
            const int nb = buf ^ 1;
            unsigned* asn = As[nb];
            asn[(ak0 + 0) * SA + ar0] = f2tf32(ra0.x);
            asn[(ak0 + 1) * SA + ar0] = f2tf32(ra0.y);
            asn[(ak0 + 2) * SA + ar0] = f2tf32(ra0.z);
            asn[(ak0 + 3) * SA + ar0] = f2tf32(ra0.w);
            asn[(ak0 + 0) * SA + ar1] = f2tf32( ra1.x);
            asn[(ak0 + 1) * SA + ar1] = f2tf32(ra1.y);
            asn[(ak0 + 2) * SA + ar1] = f2tf32(ra1.z);
            asn[(ak0 + 3) * SA + ar1] = f2tf32(ra1.w);
            uint4 b0 = make_uint4(f2tf32(rb0.x), f2tf32(rb0.y), f2tf32(rb0.z), f2tf32(rb0.w));
            uint4 b1 = make_uint4(f2tf32(rb1.x), f2tf32(rb1.y), f2tf32(rb1.z), f2tf32(rb1.w));
            *(uint4*)&Bs[nb][br0 * SA + bc0] = b0;
            *(uint4*)&Bs[nb][br1 * SA + bc0] = b1;
            __syncthreads();
        }
    }

#pragma unroll
    for (int mi = 0; mi < 2; mi++) {
#pragma unroll
        for (int ni = 0; ni < 8; ni++) {
            const int r0  = m0 + wm + mi * 16 + gid;
            const int col = n0 + wn + ni * 8 + tig * 2;
            *(float2*)(g_u2 + (size_t)r0 * 768 + col)       = make_float2(c[mi][ni][0], c[mi][ni][1]);
            *(float2*)(g_u2 + (size_t)(r0 + 8) * 768 + col) = make_float2(c[mi][ni][2], c[mi][ni][3]);
        }
    }
}

// ---------------------------------------------------------------------------
// Kernel 3: bidirectional SRU scan (k=3) + coalesced output via smem transpose
// Block 256 = 16 wp x 16 ch lanes. Grid (7 wp-chunks, 8 ch-chunks, b*2+dir).
// ---------------------------------------------------------------------------
__global__ void __launch_bounds__(256) k3_scan2(
    const float* __restrict__ wc2, const float* __restrict__ b2,
    float* __restrict__ out)
{
    const int tid = threadIdx.x;
    const int tc  = tid & 15;          // ch within group
    const int tw  = tid >> 4;          // wp within group
    const int bz  = blockIdx.z;
    const int b   = bz >> 1;
    const int dir = bz & 1;
    const int wp  = blockIdx.x * 16 + tw;
    const int cg  = blockIdx.y * 16 + tc;     // 0..127
    const int ch  = dir * D + cg;
    const int n2  = wp * 8 + b;

    const float vf = wc2[ch];
    const float vr = wc2[256 + ch];
    const float bf = b2[ch];
    const float br = b2[256 + ch];
    const float SC = 1.41421356237309515f;  // sqrt(2), rescale for k=3

    const int l0 = dir ? (L - 1) : 0;
    const int dl = dir ? -1 : 1;

    __shared__ float hs[16][17];

    // output write mapping (after transpose): lane -> (ow = wp idx, oc = ch idx)
    const int ow = tid & 15;
    const int oc = tid >> 4;
    float* obase = out + ((size_t)(b * 256 + dir * D + blockIdx.y * 16 + oc) * HP) * HP
                       + blockIdx.x * 16 + ow;

    const float* up0 = g_u2 + (size_t)n2 * 768 + (size_t)ch * 3;
    const float* ap0 = g_a2 + (size_t)n2 * 256 + ch;

    float cst = 0.0f;
    for (int s = 0; s < L; s++) {
        const int l = l0 + dl * s;
        const size_t roff = (size_t)l * NSEQ;
        const float* up = up0 + roff * 768;
        const float u0  = up[0];
        const float u1  = up[1];
        const float u2v = up[2];
        const float xp  = ap0[roff * 256] * SC;
        const float fg  = sigmoidf_(u1 + vf * cst + bf);
        cst = fg * (cst - u0) + u0;
        const float rg = sigmoidf_(u2v + vr * cst + br);
        const float h  = rg * (cst - xp) + xp;

        hs[tc][tw] = h;
        __syncthreads();
        obase[(size_t)l * HP] = hs[oc][ow];
        __syncthreads();
    }
}

// ---------------------------------------------------------------------------
extern "C" void kernel_launch(void* const* d_in, const int* in_sizes, int n_in,
                              void* d_out, int out_size)
{
    const float* x   = (const float*)d_in[0];
    const float* W1  = (const float*)d_in[1];
    const float* wc1 = (const float*)d_in[2];
    const float* b1  = (const float*)d_in[3];
    const float* W2  = (const float*)d_in[4];
    const float* wc2 = (const float*)d_in[5];
    const float* b2  = (const float*)d_in[6];
    float* out = (float*)d_out;

    k1_scan1<<<dim3(NSEQ, 2), 128>>>(x, W1, wc1, b1);
    k2_gemm_tf32<<<dim3(768 / 128, M_TOT / 128), 256>>>(W2);
    k3_scan2<<<dim3(HP / 16, 128 / 16, 16), 256>>>(wc2, b2, out);
}

// round 4
// speedup vs baseline: 2.8580x; 1.2352x over previous
#include <cuda_runtime.h>
#include <cuda_fp16.h>
#include <cmath>

// Problem constants
#define BATCH 8
#define CHN 3
#define IMG 224
#define HP 112      // Hp = Wp = 112
#define FIN 12      // patch features
#define D 128       // hidden per direction
#define L 112       // scan length (both stages)
#define NSEQ 896    // Hp*B = Wp*B
#define M_TOT (L * NSEQ)   // 100352

// Scratch (device globals — no dynamic allocation allowed)
__device__ float  g_a2 [(size_t)M_TOT * 256];   // stage-1 out (float, for k3 xprime)
__device__ __half g_a2h[(size_t)M_TOT * 256];   // stage-1 out (half, GEMM A)
__device__ __half g_w2t[(size_t)768 * 256];     // W2 transposed [n][k], half
__device__ float  g_u2 [(size_t)M_TOT * 768];   // GEMM out [l*896+n][ch*3+j]

__device__ __forceinline__ float sigmoidf_(float v) {
    return 1.0f / (1.0f + __expf(-v));
}

typedef unsigned long long u64t;
__device__ __forceinline__ u64t pack2(float a, float b) {
    u64t r; asm("mov.b64 %0,{%1,%2};" : "=l"(r) : "f"(a), "f"(b)); return r;
}
__device__ __forceinline__ u64t fma2(u64t a, u64t b, u64t c) {
    u64t d; asm("fma.rn.f32x2 %0,%1,%2,%3;" : "=l"(d) : "l"(a), "l"(b), "l"(c)); return d;
}
__device__ __forceinline__ void unpack2(u64t v, float& a, float& b) {
    asm("mov.b64 {%0,%1},%2;" : "=f"(a), "=f"(b) : "l"(v));
}

// ---------------------------------------------------------------------------
// Kernel 0: W2 (256x768 float, row-major) -> g_w2t (768x256 half, [n][k])
// ---------------------------------------------------------------------------
__global__ void __launch_bounds__(256) k0_w2half(const float* __restrict__ W2)
{
    __shared__ float t[32][33];
    const int bx = blockIdx.x * 32;   // n
    const int by = blockIdx.y * 32;   // k
    const int tx = threadIdx.x;       // 0..31
    const int ty = threadIdx.y;       // 0..7
#pragma unroll
    for (int i = 0; i < 32; i += 8)
        t[ty + i][tx] = W2[(size_t)(by + ty + i) * 768 + bx + tx];  // t[k][n]
    __syncthreads();
#pragma unroll
    for (int i = 0; i < 32; i += 8)
        g_w2t[(size_t)(bx + ty + i) * 256 + by + tx] = __float2half(t[tx][ty + i]);
}

// ---------------------------------------------------------------------------
// Kernel 1: fused patch-extract + (x @ W1) + bidirectional SRU scan (k=4)
// f32x2 packed FMA for the U projection; shfl patch broadcast.
// ---------------------------------------------------------------------------
__global__ void __launch_bounds__(128) k1_scan1(
    const float* __restrict__ x, const float* __restrict__ W1,
    const float* __restrict__ wc1, const float* __restrict__ b1)
{
    const int n1  = blockIdx.x;        // hp*8 + b
    const int dir = blockIdx.y;
    const int d   = threadIdx.x;       // 0..127 (output channel)
    const int lid = d & 31;
    const int hp  = n1 >> 3;
    const int b   = n1 & 7;

    u64t w01[FIN], w23[FIN];
    const int col0 = (dir * D + d) * 4;
#pragma unroll
    for (int f = 0; f < FIN; f++) {
        const float* wr = W1 + f * 1024 + col0;
        w01[f] = pack2(wr[0], wr[1]);
        w23[f] = pack2(wr[2], wr[3]);
    }
    const int chg = dir * D + d;
    const float vf = wc1[chg];
    const float vr = wc1[256 + chg];
    const float bf = b1[chg];
    const float br = b1[256 + chg];

    const int l0 = dir ? (L - 1) : 0;
    const int dl = dir ? -1 : 1;

    // Each warp: lanes 0..11 own one patch element (c, wh, ww)
    int xrowbase = 0, xww = 0;
    float nv = 0.0f;
    if (lid < FIN) {
        int c  = lid >> 2;
        int wh = (lid >> 1) & 1;
        xww    = lid & 1;
        xrowbase = ((b * 3 + c) * IMG + 2 * hp + wh) * IMG;
        nv = x[xrowbase + 2 * l0 + xww];
    }

    size_t oidx = ((size_t)hp * NSEQ + l0 * 8 + b) * 256 + chg;
    const ptrdiff_t ostep = (ptrdiff_t)dl * 8 * 256;

    float cst = 0.0f;
    for (int s = 0; s < L; s++) {
        const float cv = nv;
        if (lid < FIN && (s + 1) < L) {
            nv = x[xrowbase + 2 * (l0 + dl * (s + 1)) + xww];
        }
        u64t acc01 = 0ull, acc23 = 0ull;
#pragma unroll
        for (int f = 0; f < FIN; f++) {
            const float p = __shfl_sync(0xffffffffu, cv, f);
            const u64t pp = pack2(p, p);
            acc01 = fma2(pp, w01[f], acc01);
            acc23 = fma2(pp, w23[f], acc23);
        }
        float u0, u1, u2, u3;
        unpack2(acc01, u0, u1);
        unpack2(acc23, u2, u3);
        const float fg = sigmoidf_(u1 + vf * cst + bf);
        cst = fg * (cst - u0) + u0;
        const float rg = sigmoidf_(u2 + vr * cst + br);
        const float h  = rg * (cst - u3) + u3;
        g_a2 [oidx] = h;
        g_a2h[oidx] = __float2half(h);
        oidx += ostep;
    }
}

// ---------------------------------------------------------------------------
// Kernel 2: fp16 tensor-core GEMM  U2[100352,768] = a2h[100352,256] @ W2t^T
// BM=128, BN=128, BK=16; 256 threads; warp tile 32x64; mma.m16n8k16.f16.f32.
// ---------------------------------------------------------------------------
#define SAH 40   // halves per smem row (80B: conflict-free mma loads)
__global__ void __launch_bounds__(256, 2) k2_gemm_f16()
{
    __shared__ __half As[2][128 * SAH];
    __shared__ __half Bs[2][128 * SAH];

    const int tid  = threadIdx.x;
    const int lane = tid & 31;
    const int gid  = lane >> 2;     // 0..7
    const int tig  = lane & 3;      // 0..3
    const int warp = tid >> 5;
    const int wm   = (warp & 3) * 32;   // warp m offset
    const int wn   = (warp >> 2) * 64;  // warp n offset
    const int n0   = blockIdx.x * 128;
    const int m0   = blockIdx.y * 128;

    const int row = tid >> 1;           // 0..127
    const int kh  = (tid & 1) * 8;      // half-offset within 16-wide ktile

    const __half* Ag = g_a2h + (size_t)(m0 + row) * 256 + kh;
    const __half* Bg = g_w2t + (size_t)(n0 + row) * 256 + kh;

    uint4 ra = *(const uint4*)Ag;
    uint4 rb = *(const uint4*)Bg;
    *(uint4*)&As[0][row * SAH + kh] = ra;
    *(uint4*)&Bs[0][row * SAH + kh] = rb;
    __syncthreads();

    float c[2][8][4];
#pragma unroll
    for (int mi = 0; mi < 2; mi++)
#pragma unroll
        for (int ni = 0; ni < 8; ni++)
#pragma unroll
            for (int j = 0; j < 4; j++) c[mi][ni][j] = 0.f;

    for (int kt = 0; kt < 16; kt++) {
        const int buf = kt & 1;
        if (kt < 15) {
            ra = *(const uint4*)(Ag + (kt + 1) * 16);
            rb = *(const uint4*)(Bg + (kt + 1) * 16);
        }

        const __half* as = As[buf];
        const __half* bs = Bs[buf];
        unsigned a[2][4];
#pragma unroll
        for (int mi = 0; mi < 2; mi++) {
            const int mb = wm + mi * 16 + gid;
            a[mi][0] = *(const unsigned*)&as[mb * SAH + 2 * tig];
            a[mi][1] = *(const unsigned*)&as[(mb + 8) * SAH + 2 * tig];
            a[mi][2] = *(const unsigned*)&as[mb * SAH + 2 * tig + 8];
            a[mi][3] = *(const unsigned*)&as[(mb + 8) * SAH + 2 * tig + 8];
        }
#pragma unroll
        for (int ni = 0; ni < 8; ni++) {
            const int nb = wn + ni * 8 + gid;
            const unsigned b0 = *(const unsigned*)&bs[nb * SAH + 2 * tig];
            const unsigned b1 = *(const unsigned*)&bs[nb * SAH + 2 * tig + 8];
#pragma unroll
            for (int mi = 0; mi < 2; mi++) {
                asm volatile(
                    "mma.sync.aligned.m16n8k16.row.col.f32.f16.f16.f32 "
                    "{%0,%1,%2,%3}, {%4,%5,%6,%7}, {%8,%9}, {%0,%1,%2,%3};"
                    : "+f"(c[mi][ni][0]), "+f"(c[mi][ni][1]),
                      "+f"(c[mi][ni][2]), "+f"(c[mi][ni][3])
                    : "r"(a[mi][0]), "r"(a[mi][1]), "r"(a[mi][2]), "r"(a[mi][3]),
                      "r"(b0), "r"(b1));
            }
        }

        if (kt < 15) {
            const int nb = buf ^ 1;
            *(uint4*)&As[nb][row * SAH + kh] = ra;
            *(uint4*)&Bs[nb][row * SAH + kh] = rb;
            __syncthreads();
        }
    }

#pragma unroll
    for (int mi = 0; mi < 2; mi++) {
#pragma unroll
        for (int ni = 0; ni < 8; ni++) {
            const int r0  = m0 + wm + mi * 16 + gid;
            const int col = n0 + wn + ni * 8 + tig * 2;
            *(float2*)(g_u2 + (size_t)r0 * 768 + col)       = make_float2(c[mi][ni][0], c[mi][ni][1]);
            *(float2*)(g_u2 + (size_t)(r0 + 8) * 768 + col) = make_float2(c[mi][ni][2], c[mi][ni][3]);
        }
    }
}

// ---------------------------------------------------------------------------
// Kernel 3: bidirectional SRU scan (k=3) + coalesced output, 8-step batched
// transpose. Block 256 = 16 wp x 16 ch. Grid (7, 8, b*2+dir).
// ---------------------------------------------------------------------------
__global__ void __launch_bounds__(256) k3_scan2(
    const float* __restrict__ wc2, const float* __restrict__ b2,
    float* __restrict__ out)
{
    const int tid = threadIdx.x;
    const int tc  = tid & 15;          // ch within group
    const int tw  = tid >> 4;          // wp within group
    const int bz  = blockIdx.z;
    const int b   = bz >> 1;
    const int dir = bz & 1;
    const int wp  = blockIdx.x * 16 + tw;
    const int cg  = blockIdx.y * 16 + tc;     // 0..127
    const int ch  = dir * D + cg;
    const int n2  = wp * 8 + b;

    const float vf = wc2[ch];
    const float vr = wc2[256 + ch];
    const float bf = b2[ch];
    const float br = b2[256 + ch];
    const float SC = 1.41421356237309515f;  // sqrt(2), rescale for k=3

    const int l0 = dir ? (L - 1) : 0;
    const int dl = dir ? -1 : 1;

    __shared__ float hs[8][16][17];

    // output write mapping (after transpose)
    const int ow = tid & 15;
    const int oc = tid >> 4;
    float* obase = out + ((size_t)(b * 256 + dir * D + blockIdx.y * 16 + oc) * HP) * HP
                       + blockIdx.x * 16 + ow;

    const float* up0 = g_u2 + (size_t)n2 * 768 + (size_t)ch * 3;
    const float* ap0 = g_a2 + (size_t)n2 * 256 + ch;

    float cst = 0.0f;
    for (int s0 = 0; s0 < L; s0 += 8) {
#pragma unroll
        for (int j = 0; j < 8; j++) {
            const int l = l0 + dl * (s0 + j);
            const size_t roff = (size_t)l * NSEQ;
            const float* up = up0 + roff * 768;
            const float u0  = up[0];
            const float u1  = up[1];
            const float u2v = up[2];
            const float xp  = ap0[roff * 256] * SC;
            const float fg  = sigmoidf_(u1 + vf * cst + bf);
            cst = fg * (cst - u0) + u0;
            const float rg = sigmoidf_(u2v + vr * cst + br);
            hs[j][tc][tw] = rg * (cst - xp) + xp;
        }
        __syncthreads();
#pragma unroll
        for (int j = 0; j < 8; j++) {
            const int l = l0 + dl * (s0 + j);
            obase[(size_t)l * HP] = hs[j][oc][ow];
        }
        __syncthreads();
    }
}

// ---------------------------------------------------------------------------
extern "C" void kernel_launch(void* const* d_in, const int* in_sizes, int n_in,
                              void* d_out, int out_size)
{
    const float* x   = (const float*)d_in[0];
    const float* W1  = (const float*)d_in[1];
    const float* wc1 = (const float*)d_in[2];
    const float* b1  = (const float*)d_in[3];
    const float* W2  = (const float*)d_in[4];
    const float* wc2 = (const float*)d_in[5];
    const float* b2  = (const float*)d_in[6];
    float* out = (float*)d_out;

    k0_w2half<<<dim3(768 / 32, 256 / 32), dim3(32, 8)>>>(W2);
    k1_scan1<<<dim3(NSEQ, 2), 128>>>(x, W1, wc1, b1);
    k2_gemm_f16<<<dim3(768 / 128, M_TOT / 128), 256>>>();
    k3_scan2<<<dim3(HP / 16, 128 / 16, 16), 256>>>(wc2, b2, out);
}

// round 5
// speedup vs baseline: 3.1776x; 1.1118x over previous
#include <cuda_runtime.h>
#include <cuda_fp16.h>
#include <cmath>

// Problem constants
#define BATCH 8
#define CHN 3
#define IMG 224
#define HP 112      // Hp = Wp = 112
#define FIN 12      // patch features
#define D 128       // hidden per direction
#define L 112       // scan length (both stages)
#define NSEQ 896    // Hp*B = Wp*B
#define M_TOT (L * NSEQ)   // 100352

// Scratch (device globals — no dynamic allocation allowed)
__device__ __half g_a2h[(size_t)M_TOT * 256];   // stage-1 out (half): GEMM A + k3 xprime
__device__ __half g_w2t[(size_t)768 * 256];     // W2 transposed+permuted [j*256+ch][k], half
__device__ __half g_u2h[(size_t)M_TOT * 768];   // GEMM out, cols j*256+ch (j-major!)

__device__ __forceinline__ float sigmoidf_(float v) {
    float t;
    asm("tanh.approx.f32 %0, %1;" : "=f"(t) : "f"(v * 0.5f));
    return fmaf(t, 0.5f, 0.5f);
}

typedef unsigned long long u64t;
__device__ __forceinline__ u64t pack2(float a, float b) {
    u64t r; asm("mov.b64 %0,{%1,%2};" : "=l"(r) : "f"(a), "f"(b)); return r;
}
__device__ __forceinline__ u64t fma2(u64t a, u64t b, u64t c) {
    u64t d; asm("fma.rn.f32x2 %0,%1,%2,%3;" : "=l"(d) : "l"(a), "l"(b), "l"(c)); return d;
}
__device__ __forceinline__ void unpack2(u64t v, float& a, float& b) {
    asm("mov.b64 {%0,%1},%2;" : "=f"(a), "=f"(b) : "l"(v));
}

// ---------------------------------------------------------------------------
// Kernel 0: W2[k][n] (256x768 f32) -> g_w2t[n'][k] half, n' = (n%3)*256 + n/3
// (j-major output columns so k3's u0/u1/u2 reads are coalesced)
// ---------------------------------------------------------------------------
__global__ void __launch_bounds__(256) k0_w2half(const float* __restrict__ W2)
{
    const int idx = blockIdx.x * 256 + threadIdx.x;  // k*768 + n
    const int k = idx / 768;
    const int n = idx % 768;
    const int np = (n % 3) * 256 + n / 3;
    g_w2t[(size_t)np * 256 + k] = __float2half(W2[idx]);
}

// ---------------------------------------------------------------------------
// Kernel 1: fused patch-extract + (x @ W1) + bidirectional SRU scan (k=4)
// f32x2 packed FMA; shfl patch broadcast; half output only.
// ---------------------------------------------------------------------------
__global__ void __launch_bounds__(128) k1_scan1(
    const float* __restrict__ x, const float* __restrict__ W1,
    const float* __restrict__ wc1, const float* __restrict__ b1)
{
    const int n1  = blockIdx.x;        // hp*8 + b
    const int dir = blockIdx.y;
    const int d   = threadIdx.x;       // 0..127 (output channel)
    const int lid = d & 31;
    const int hp  = n1 >> 3;
    const int b   = n1 & 7;

    u64t w01[FIN], w23[FIN];
    const int col0 = (dir * D + d) * 4;
#pragma unroll
    for (int f = 0; f < FIN; f++) {
        const float* wr = W1 + f * 1024 + col0;
        w01[f] = pack2(wr[0], wr[1]);
        w23[f] = pack2(wr[2], wr[3]);
    }
    const int chg = dir * D + d;
    const float vf = wc1[chg];
    const float vr = wc1[256 + chg];
    const float bf = b1[chg];
    const float br = b1[256 + chg];

    const int l0 = dir ? (L - 1) : 0;
    const int dl = dir ? -1 : 1;

    // Each warp: lanes 0..11 own one patch element (c, wh, ww)
    int xrowbase = 0, xww = 0;
    float nv = 0.0f;
    if (lid < FIN) {
        int c  = lid >> 2;
        int wh = (lid >> 1) & 1;
        xww    = lid & 1;
        xrowbase = ((b * 3 + c) * IMG + 2 * hp + wh) * IMG;
        nv = x[xrowbase + 2 * l0 + xww];
    }

    size_t oidx = ((size_t)hp * NSEQ + l0 * 8 + b) * 256 + chg;
    const ptrdiff_t ostep = (ptrdiff_t)dl * 8 * 256;

    float cst = 0.0f;
    for (int s = 0; s < L; s++) {
        const float cv = nv;
        if (lid < FIN && (s + 1) < L) {
            nv = x[xrowbase + 2 * (l0 + dl * (s + 1)) + xww];
        }
        u64t acc01 = 0ull, acc23 = 0ull;
#pragma unroll
        for (int f = 0; f < FIN; f++) {
            const float p = __shfl_sync(0xffffffffu, cv, f);
            const u64t pp = pack2(p, p);
            acc01 = fma2(pp, w01[f], acc01);
            acc23 = fma2(pp, w23[f], acc23);
        }
        float u0, u1, u2, u3;
        unpack2(acc01, u0, u1);
        unpack2(acc23, u2, u3);
        const float fg = sigmoidf_(u1 + vf * cst + bf);
        cst = fg * (cst - u0) + u0;
        const float rg = sigmoidf_(u2 + vr * cst + br);
        const float h  = rg * (cst - u3) + u3;
        g_a2h[oidx] = __float2half(h);
        oidx += ostep;
    }
}

// ---------------------------------------------------------------------------
// Kernel 2: fp16 tensor-core GEMM  U2[100352,768] = a2h[100352,256] @ W2t^T
// BM=128, BN=128, BK=16; 256 threads; warp tile 32x64; mma.m16n8k16.f16.f32.
// fp16 output stores.
// ---------------------------------------------------------------------------
#define SAH 40   // halves per smem row (80B: conflict-free mma loads)
__global__ void __launch_bounds__(256, 2) k2_gemm_f16()
{
    __shared__ __half As[2][128 * SAH];
    __shared__ __half Bs[2][128 * SAH];

    const int tid  = threadIdx.x;
    const int lane = tid & 31;
    const int gid  = lane >> 2;     // 0..7
    const int tig  = lane & 3;      // 0..3
    const int warp = tid >> 5;
    const int wm   = (warp & 3) * 32;   // warp m offset
    const int wn   = (warp >> 2) * 64;  // warp n offset
    const int n0   = blockIdx.x * 128;
    const int m0   = blockIdx.y * 128;

    const int row = tid >> 1;           // 0..127
    const int kh  = (tid & 1) * 8;      // half-offset within 16-wide ktile

    const __half* Ag = g_a2h + (size_t)(m0 + row) * 256 + kh;
    const __half* Bg = g_w2t + (size_t)(n0 + row) * 256 + kh;

    uint4 ra = *(const uint4*)Ag;
    uint4 rb = *(const uint4*)Bg;
    *(uint4*)&As[0][row * SAH + kh] = ra;
    *(uint4*)&Bs[0][row * SAH + kh] = rb;
    __syncthreads();

    float c[2][8][4];
#pragma unroll
    for (int mi = 0; mi < 2; mi++)
#pragma unroll
        for (int ni = 0; ni < 8; ni++)
#pragma unroll
            for (int j = 0; j < 4; j++) c[mi][ni][j] = 0.f;

    for (int kt = 0; kt < 16; kt++) {
        const int buf = kt & 1;
        if (kt < 15) {
            ra = *(const uint4*)(Ag + (kt + 1) * 16);
            rb = *(const uint4*)(Bg + (kt + 1) * 16);
        }

        const __half* as = As[buf];
        const __half* bs = Bs[buf];
        unsigned a[2][4];
#pragma unroll
        for (int mi = 0; mi < 2; mi++) {
            const int mb = wm + mi * 16 + gid;
            a[mi][0] = *(const unsigned*)&as[mb * SAH + 2 * tig];
            a[mi][1] = *(const unsigned*)&as[(mb + 8) * SAH + 2 * tig];
            a[mi][2] = *(const unsigned*)&as[mb * SAH + 2 * tig + 8];
            a[mi][3] = *(const unsigned*)&as[(mb + 8) * SAH + 2 * tig + 8];
        }
#pragma unroll
        for (int ni = 0; ni < 8; ni++) {
            const int nb = wn + ni * 8 + gid;
            const unsigned b0 = *(const unsigned*)&bs[nb * SAH + 2 * tig];
            const unsigned b1 = *(const unsigned*)&bs[nb * SAH + 2 * tig + 8];
#pragma unroll
            for (int mi = 0; mi < 2; mi++) {
                asm volatile(
                    "mma.sync.aligned.m16n8k16.row.col.f32.f16.f16.f32 "
                    "{%0,%1,%2,%3}, {%4,%5,%6,%7}, {%8,%9}, {%0,%1,%2,%3};"
                    : "+f"(c[mi][ni][0]), "+f"(c[mi][ni][1]),
                      "+f"(c[mi][ni][2]), "+f"(c[mi][ni][3])
                    : "r"(a[mi][0]), "r"(a[mi][1]), "r"(a[mi][2]), "r"(a[mi][3]),
                      "r"(b0), "r"(b1));
            }
        }

        if (kt < 15) {
            const int nb = buf ^ 1;
            *(uint4*)&As[nb][row * SAH + kh] = ra;
            *(uint4*)&Bs[nb][row * SAH + kh] = rb;
            __syncthreads();
        }
    }

#pragma unroll
    for (int mi = 0; mi < 2; mi++) {
#pragma unroll
        for (int ni = 0; ni < 8; ni++) {
            const int r0  = m0 + wm + mi * 16 + gid;
            const int col = n0 + wn + ni * 8 + tig * 2;
            *(__half2*)(g_u2h + (size_t)r0 * 768 + col) =
                __floats2half2_rn(c[mi][ni][0], c[mi][ni][1]);
            *(__half2*)(g_u2h + (size_t)(r0 + 8) * 768 + col) =
                __floats2half2_rn(c[mi][ni][2], c[mi][ni][3]);
        }
    }
}

// ---------------------------------------------------------------------------
// Kernel 3: bidirectional SRU scan (k=3) + coalesced output, 8-step batched
// transpose. Block 256 = 16 wp x 16 ch. Grid (7, 8, b*2+dir). fp16 inputs.
// ---------------------------------------------------------------------------
__global__ void __launch_bounds__(256) k3_scan2(
    const float* __restrict__ wc2, const float* __restrict__ b2,
    float* __restrict__ out)
{
    const int tid = threadIdx.x;
    const int tc  = tid & 15;          // ch within group
    const int tw  = tid >> 4;          // wp within group
    const int bz  = blockIdx.z;
    const int b   = bz >> 1;
    const int dir = bz & 1;
    const int wp  = blockIdx.x * 16 + tw;
    const int cg  = blockIdx.y * 16 + tc;     // 0..127
    const int ch  = dir * D + cg;
    const int n2  = wp * 8 + b;

    const float vf = wc2[ch];
    const float vr = wc2[256 + ch];
    const float bf = b2[ch];
    const float br = b2[256 + ch];
    const float SC = 1.41421356237309515f;  // sqrt(2), rescale for k=3

    const int l0 = dir ? (L - 1) : 0;
    const int dl = dir ? -1 : 1;

    __shared__ float hs[8][16][17];

    // output write mapping (after transpose)
    const int ow = tid & 15;
    const int oc = tid >> 4;
    float* obase = out + ((size_t)(b * 256 + dir * D + blockIdx.y * 16 + oc) * HP) * HP
                       + blockIdx.x * 16 + ow;

    // u2h columns are j-major: u_j at offset j*256 + ch
    const __half* up0 = g_u2h + (size_t)n2 * 768 + ch;
    const __half* ap0 = g_a2h + (size_t)n2 * 256 + ch;

    float cst = 0.0f;
    for (int s0 = 0; s0 < L; s0 += 8) {
#pragma unroll
        for (int j = 0; j < 8; j++) {
            const int l = l0 + dl * (s0 + j);
            const size_t roff = (size_t)l * NSEQ;
            const __half* up = up0 + roff * 768;
            const float u0  = __half2float(up[0]);
            const float u1  = __half2float(up[256]);
            const float u2v = __half2float(up[512]);
            const float xp  = __half2float(ap0[roff * 256]) * SC;
            const float fg  = sigmoidf_(u1 + vf * cst + bf);
            cst = fg * (cst - u0) + u0;
            const float rg = sigmoidf_(u2v + vr * cst + br);
            hs[j][tc][tw] = rg * (cst - xp) + xp;
        }
        __syncthreads();
#pragma unroll
        for (int j = 0; j < 8; j++) {
            const int l = l0 + dl * (s0 + j);
            obase[(size_t)l * HP] = hs[j][oc][ow];
        }
        __syncthreads();
    }
}

// ---------------------------------------------------------------------------
extern "C" void kernel_launch(void* const* d_in, const int* in_sizes, int n_in,
                              void* d_out, int out_size)
{
    const float* x   = (const float*)d_in[0];
    const float* W1  = (const float*)d_in[1];
    const float* wc1 = (const float*)d_in[2];
    const float* b1  = (const float*)d_in[3];
    const float* W2  = (const float*)d_in[4];
    const float* wc2 = (const float*)d_in[5];
    const float* b2  = (const float*)d_in[6];
    float* out = (float*)d_out;

    k0_w2half<<<768, 256>>>(W2);
    k1_scan1<<<dim3(NSEQ, 2), 128>>>(x, W1, wc1, b1);
    k2_gemm_f16<<<dim3(768 / 128, M_TOT / 128), 256>>>();
    k3_scan2<<<dim3(HP / 16, 128 / 16, 16), 256>>>(wc2, b2, out);
}

// round 6
// speedup vs baseline: 3.4324x; 1.0802x over previous
#include <cuda_runtime.h>
#include <cuda_fp16.h>
#include <cmath>

// Problem constants
#define BATCH 8
#define CHN 3
#define IMG 224
#define HP 112      // Hp = Wp = 112
#define FIN 12      // patch features
#define D 128       // hidden per direction
#define L 112       // scan length (both stages)
#define NSEQ 896    // Hp*B = Wp*B
#define M_TOT (L * NSEQ)   // 100352

// Scratch (device globals — no dynamic allocation allowed)
__device__ __half g_a2h[(size_t)M_TOT * 256];   // stage-1 out (half): GEMM A + k3 xprime
__device__ __half g_w2t[(size_t)768 * 256];     // W2 transposed+permuted [j*256+ch][k], half
__device__ __half g_u2h[(size_t)M_TOT * 768];   // GEMM out, cols j*256+ch (j-major)

__device__ __forceinline__ float sigmoidf_(float v) {
    float t;
    asm("tanh.approx.f32 %0, %1;" : "=f"(t) : "f"(v * 0.5f));
    return fmaf(t, 0.5f, 0.5f);
}

typedef unsigned long long u64t;
__device__ __forceinline__ u64t pack2(float a, float b) {
    u64t r; asm("mov.b64 %0,{%1,%2};" : "=l"(r) : "f"(a), "f"(b)); return r;
}
__device__ __forceinline__ u64t fma2(u64t a, u64t b, u64t c) {
    u64t d; asm("fma.rn.f32x2 %0,%1,%2,%3;" : "=l"(d) : "l"(a), "l"(b), "l"(c)); return d;
}
__device__ __forceinline__ void unpack2(u64t v, float& a, float& b) {
    asm("mov.b64 {%0,%1},%2;" : "=f"(a), "=f"(b) : "l"(v));
}

#define LDSM4(r0, r1, r2, r3, addr) \
    asm volatile("ldmatrix.sync.aligned.m8n8.x4.shared.b16 {%0,%1,%2,%3},[%4];" \
                 : "=r"(r0), "=r"(r1), "=r"(r2), "=r"(r3) : "r"(addr))

// ---------------------------------------------------------------------------
// Kernel 0: W2[k][n] (256x768 f32) -> g_w2t[n'][k] half, n' = (n%3)*256 + n/3
// ---------------------------------------------------------------------------
__global__ void __launch_bounds__(256) k0_w2half(const float* __restrict__ W2)
{
    const int idx = blockIdx.x * 256 + threadIdx.x;  // k*768 + n
    const int k = idx / 768;
    const int n = idx % 768;
    const int np = (n % 3) * 256 + n / 3;
    g_w2t[(size_t)np * 256 + k] = __float2half(W2[idx]);
}

// ---------------------------------------------------------------------------
// Kernel 1: fused patch-extract + (x @ W1) + bidirectional SRU scan (k=4)
// ---------------------------------------------------------------------------
__global__ void __launch_bounds__(128) k1_scan1(
    const float* __restrict__ x, const float* __restrict__ W1,
    const float* __restrict__ wc1, const float* __restrict__ b1)
{
    const int n1  = blockIdx.x;        // hp*8 + b
    const int dir = blockIdx.y;
    const int d   = threadIdx.x;       // 0..127 (output channel)
    const int lid = d & 31;
    const int hp  = n1 >> 3;
    const int b   = n1 & 7;

    u64t w01[FIN], w23[FIN];
    const int col0 = (dir * D + d) * 4;
#pragma unroll
    for (int f = 0; f < FIN; f++) {
        const float* wr = W1 + f * 1024 + col0;
        w01[f] = pack2(wr[0], wr[1]);
        w23[f] = pack2(wr[2], wr[3]);
    }
    const int chg = dir * D + d;
    const float vf = wc1[chg];
    const float vr = wc1[256 + chg];
    const float bf = b1[chg];
    const float br = b1[256 + chg];

    const int l0 = dir ? (L - 1) : 0;
    const int dl = dir ? -1 : 1;

    int xrowbase = 0, xww = 0;
    float nv = 0.0f;
    if (lid < FIN) {
        int c  = lid >> 2;
        int wh = (lid >> 1) & 1;
        xww    = lid & 1;
        xrowbase = ((b * 3 + c) * IMG + 2 * hp + wh) * IMG;
        nv = x[xrowbase + 2 * l0 + xww];
    }

    size_t oidx = ((size_t)hp * NSEQ + l0 * 8 + b) * 256 + chg;
    const ptrdiff_t ostep = (ptrdiff_t)dl * 8 * 256;

    float cst = 0.0f;
    for (int s = 0; s < L; s++) {
        const float cv = nv;
        if (lid < FIN && (s + 1) < L) {
            nv = x[xrowbase + 2 * (l0 + dl * (s + 1)) + xww];
        }
        u64t acc01 = 0ull, acc23 = 0ull;
#pragma unroll
        for (int f = 0; f < FIN; f++) {
            const float p = __shfl_sync(0xffffffffu, cv, f);
            const u64t pp = pack2(p, p);
            acc01 = fma2(pp, w01[f], acc01);
            acc23 = fma2(pp, w23[f], acc23);
        }
        float u0, u1, u2, u3;
        unpack2(acc01, u0, u1);
        unpack2(acc23, u2, u3);
        const float fg = sigmoidf_(u1 + vf * cst + bf);
        cst = fg * (cst - u0) + u0;
        const float rg = sigmoidf_(u2 + vr * cst + br);
        const float h  = rg * (cst - u3) + u3;
        g_a2h[oidx] = __float2half(h);
        oidx += ostep;
    }
}

// ---------------------------------------------------------------------------
// Kernel 2: fp16 GEMM  U2[100352,768] = a2h @ w2t^T
// BM=128, BN=128, BK=32; 256 threads; warp tile 32x64; ldmatrix + m16n8k16.
// ---------------------------------------------------------------------------
#define SAH 40                 // halfs per smem row (80 B, LDSM conflict-free)
#define ABUF (128 * SAH * 2)   // bytes per buffer
__global__ void __launch_bounds__(256, 2) k2_gemm_f16()
{
    __shared__ __half As[2][128 * SAH];
    __shared__ __half Bs[2][128 * SAH];

    const int tid  = threadIdx.x;
    const int lane = tid & 31;
    const int gid  = lane >> 2;     // 0..7
    const int tig  = lane & 3;      // 0..3
    const int warp = tid >> 5;
    const int wm   = (warp & 3) * 32;   // warp m offset
    const int wn   = (warp >> 2) * 64;  // warp n offset
    const int n0   = blockIdx.x * 128;
    const int m0   = blockIdx.y * 128;

    const int row = tid >> 1;           // 0..127
    const int kc  = (tid & 1) * 16;     // half-offset within 32-wide ktile

    const __half* Ag = g_a2h + (size_t)(m0 + row) * 256 + kc;
    const __half* Bg = g_w2t + (size_t)(n0 + row) * 256 + kc;

    // ldmatrix base addresses (buf 0, kk = 0)
    unsigned aAddr = (unsigned)__cvta_generic_to_shared(&As[0][0])
        + (((wm + (lane & 7) + (lane & 8)) * SAH + ((lane & 16) ? 8 : 0)) * 2);
    unsigned bAddr = (unsigned)__cvta_generic_to_shared(&Bs[0][0])
        + (((wn + (lane & 7) + ((lane & 16) ? 8 : 0)) * SAH + ((lane & 8) ? 8 : 0)) * 2);

    // prologue: ktile 0
    uint4 ra0 = *(const uint4*)Ag;
    uint4 ra1 = *(const uint4*)(Ag + 8);
    uint4 rb0 = *(const uint4*)Bg;
    uint4 rb1 = *(const uint4*)(Bg + 8);
    *(uint4*)&As[0][row * SAH + kc]     = ra0;
    *(uint4*)&As[0][row * SAH + kc + 8] = ra1;
    *(uint4*)&Bs[0][row * SAH + kc]     = rb0;
    *(uint4*)&Bs[0][row * SAH + kc + 8] = rb1;
    __syncthreads();

    float c[2][8][4];
#pragma unroll
    for (int mi = 0; mi < 2; mi++)
#pragma unroll
        for (int ni = 0; ni < 8; ni++)
#pragma unroll
            for (int j = 0; j < 4; j++) c[mi][ni][j] = 0.f;

    for (int kt = 0; kt < 8; kt++) {
        const int buf = kt & 1;
        if (kt < 7) {
            const int k0 = (kt + 1) * 32;
            ra0 = *(const uint4*)(Ag + k0);
            ra1 = *(const uint4*)(Ag + k0 + 8);
            rb0 = *(const uint4*)(Bg + k0);
            rb1 = *(const uint4*)(Bg + k0 + 8);
        }

        const unsigned aB = aAddr + buf * ABUF;
        const unsigned bB = bAddr + buf * ABUF;
#pragma unroll
        for (int kk = 0; kk < 32; kk += 16) {
            unsigned a[2][4];
#pragma unroll
            for (int mi = 0; mi < 2; mi++)
                LDSM4(a[mi][0], a[mi][1], a[mi][2], a[mi][3],
                      aB + mi * (16 * SAH * 2) + kk * 2);
#pragma unroll
            for (int nt = 0; nt < 4; nt++) {
                unsigned b00, b01, b10, b11;
                LDSM4(b00, b01, b10, b11, bB + nt * (16 * SAH * 2) + kk * 2);
#pragma unroll
                for (int mi = 0; mi < 2; mi++) {
                    asm volatile(
                        "mma.sync.aligned.m16n8k16.row.col.f32.f16.f16.f32 "
                        "{%0,%1,%2,%3}, {%4,%5,%6,%7}, {%8,%9}, {%0,%1,%2,%3};"
                        : "+f"(c[mi][2 * nt][0]), "+f"(c[mi][2 * nt][1]),
                          "+f"(c[mi][2 * nt][2]), "+f"(c[mi][2 * nt][3])
                        : "r"(a[mi][0]), "r"(a[mi][1]), "r"(a[mi][2]), "r"(a[mi][3]),
                          "r"(b00), "r"(b01));
                    asm volatile(
                        "mma.sync.aligned.m16n8k16.row.col.f32.f16.f16.f32 "
                        "{%0,%1,%2,%3}, {%4,%5,%6,%7}, {%8,%9}, {%0,%1,%2,%3};"
                        : "+f"(c[mi][2 * nt + 1][0]), "+f"(c[mi][2 * nt + 1][1]),
                          "+f"(c[mi][2 * nt + 1][2]), "+f"(c[mi][2 * nt + 1][3])
                        : "r"(a[mi][0]), "r"(a[mi][1]), "r"(a[mi][2]), "r"(a[mi][3]),
                          "r"(b10), "r"(b11));
                }
            }
        }

        if (kt < 7) {
            const int nb = buf ^ 1;
            __syncthreads();   // everyone done reading buffer nb from 2 iters ago
            *(uint4*)&As[nb][row * SAH + kc]     = ra0;
            *(uint4*)&As[nb][row * SAH + kc + 8] = ra1;
            *(uint4*)&Bs[nb][row * SAH + kc]     = rb0;
            *(uint4*)&Bs[nb][row * SAH + kc + 8] = rb1;
            __syncthreads();
        }
    }

#pragma unroll
    for (int mi = 0; mi < 2; mi++) {
#pragma unroll
        for (int ni = 0; ni < 8; ni++) {
            const int r0  = m0 + wm + mi * 16 + gid;
            const int col = n0 + wn + ni * 8 + tig * 2;
            *(__half2*)(g_u2h + (size_t)r0 * 768 + col) =
                __floats2half2_rn(c[mi][ni][0], c[mi][ni][1]);
            *(__half2*)(g_u2h + (size_t)(r0 + 8) * 768 + col) =
                __floats2half2_rn(c[mi][ni][2], c[mi][ni][3]);
        }
    }
}

// ---------------------------------------------------------------------------
// Kernel 3: bidirectional SRU scan (k=3) + coalesced output. Software-
// pipelined: group g+1's loads issue while group g computes/transposes.
// Block 256 = 16 wp x 16 ch. Grid (7, 8, b*2+dir).
// ---------------------------------------------------------------------------
__global__ void __launch_bounds__(256) k3_scan2(
    const float* __restrict__ wc2, const float* __restrict__ b2,
    float* __restrict__ out)
{
    const int tid = threadIdx.x;
    const int tc  = tid & 15;          // ch within group
    const int tw  = tid >> 4;          // wp within group
    const int bz  = blockIdx.z;
    const int b   = bz >> 1;
    const int dir = bz & 1;
    const int wp  = blockIdx.x * 16 + tw;
    const int cg  = blockIdx.y * 16 + tc;     // 0..127
    const int ch  = dir * D + cg;
    const int n2  = wp * 8 + b;

    const float vf = wc2[ch];
    const float vr = wc2[256 + ch];
    const float bf = b2[ch];
    const float br = b2[256 + ch];
    const float SC = 1.41421356237309515f;  // sqrt(2), rescale for k=3

    const int l0 = dir ? (L - 1) : 0;
    const int dl = dir ? -1 : 1;

    __shared__ float hs[8][16][17];

    const int ow = tid & 15;
    const int oc = tid >> 4;
    float* obase = out + ((size_t)(b * 256 + dir * D + blockIdx.y * 16 + oc) * HP) * HP
                       + blockIdx.x * 16 + ow;

    const ptrdiff_t ustep = (ptrdiff_t)dl * (NSEQ * 768);
    const ptrdiff_t astep = (ptrdiff_t)dl * (NSEQ * 256);
    const __half* ub = g_u2h + ((size_t)l0 * NSEQ + n2) * 768 + ch;  // s = 0
    const __half* ab = g_a2h + ((size_t)l0 * NSEQ + n2) * 256 + ch;

    __half cu0[8], cu1[8], cu2[8], cxp[8];
    __half pu0[8], pu1[8], pu2[8], pxp[8];

#pragma unroll
    for (int j = 0; j < 8; j++) {
        const __half* up = ub + (ptrdiff_t)j * ustep;
        cu0[j] = up[0];
        cu1[j] = up[256];
        cu2[j] = up[512];
        cxp[j] = ab[(ptrdiff_t)j * astep];
    }

    float cst = 0.0f;
#pragma unroll 2
    for (int g = 0; g < 14; g++) {
        if (g < 13) {
#pragma unroll
            for (int j = 0; j < 8; j++) {
                const int s = (g + 1) * 8 + j;
                const __half* up = ub + (ptrdiff_t)s * ustep;
                pu0[j] = up[0];
                pu1[j] = up[256];
                pu2[j] = up[512];
                pxp[j] = ab[(ptrdiff_t)s * astep];
            }
        }
#pragma unroll
        for (int j = 0; j < 8; j++) {
            const float u0  = __half2float(cu0[j]);
            const float u1  = __half2float(cu1[j]);
            const float u2v = __half2float(cu2[j]);
            const float xp  = __half2float(cxp[j]) * SC;
            const float fg  = sigmoidf_(u1 + vf * cst + bf);
            cst = fg * (cst - u0) + u0;
            const float rg = sigmoidf_(u2v + vr * cst + br);
            hs[j][tc][tw] = rg * (cst - xp) + xp;
        }
        __syncthreads();
#pragma unroll
        for (int j = 0; j < 8; j++) {
            const int l = l0 + dl * (g * 8 + j);
            obase[(size_t)l * HP] = hs[j][oc][ow];
        }
        __syncthreads();
#pragma unroll
        for (int j = 0; j < 8; j++) {
            cu0[j] = pu0[j];
            cu1[j] = pu1[j];
            cu2[j] = pu2[j];
            cxp[j] = pxp[j];
        }
    }
}

// ---------------------------------------------------------------------------
extern "C" void kernel_launch(void* const* d_in, const int* in_sizes, int n_in,
                              void* d_out, int out_size)
{
    const float* x   = (const float*)d_in[0];
    const float* W1  = (const float*)d_in[1];
    const float* wc1 = (const float*)d_in[2];
    const float* b1  = (const float*)d_in[3];
    const float* W2  = (const float*)d_in[4];
    const float* wc2 = (const float*)d_in[5];
    const float* b2  = (const float*)d_in[6];
    float* out = (float*)d_out;

    k0_w2half<<<768, 256>>>(W2);
    k1_scan1<<<dim3(NSEQ, 2), 128>>>(x, W1, wc1, b1);
    k2_gemm_f16<<<dim3(768 / 128, M_TOT / 128), 256>>>();
    k3_scan2<<<dim3(HP / 16, 128 / 16, 16), 256>>>(wc2, b2, out);
}

// round 8
// speedup vs baseline: 4.1082x; 1.1969x over previous
#include <cuda_runtime.h>
#include <cuda_fp16.h>
#include <cstdint>
#include <cmath>

// Problem constants
#define BATCH 8
#define CHN 3
#define IMG 224
#define HP 112      // Hp = Wp = 112
#define FIN 12      // patch features
#define D 128       // hidden per direction
#define L 112       // scan length (both stages)
#define NSEQ 896    // Hp*B = Wp*B
#define M_TOT (L * NSEQ)   // 100352

// Scratch (device globals — no dynamic allocation allowed)
__device__ __half g_a2h[(size_t)M_TOT * 256];   // stage-1 out (half): GEMM A + k3 xprime
__device__ __half g_w2t[(size_t)768 * 256];     // W2 transposed+permuted [j*256+ch][k], half
__device__ __half g_u2h[(size_t)M_TOT * 768];   // GEMM out, cols j*256+ch (j-major)

__device__ __forceinline__ float sigmoidf_(float v) {
    float t;
    asm("tanh.approx.f32 %0, %1;" : "=f"(t) : "f"(v * 0.5f));
    return fmaf(t, 0.5f, 0.5f);
}

typedef unsigned long long u64t;
__device__ __forceinline__ u64t pack2(float a, float b) {
    u64t r; asm("mov.b64 %0,{%1,%2};" : "=l"(r) : "f"(a), "f"(b)); return r;
}
__device__ __forceinline__ u64t fma2(u64t a, u64t b, u64t c) {
    u64t d; asm("fma.rn.f32x2 %0,%1,%2,%3;" : "=l"(d) : "l"(a), "l"(b), "l"(c)); return d;
}
__device__ __forceinline__ void unpack2(u64t v, float& a, float& b) {
    asm("mov.b64 {%0,%1},%2;" : "=f"(a), "=f"(b) : "l"(v));
}

#define LDSM4(r0, r1, r2, r3, addr) \
    asm volatile("ldmatrix.sync.aligned.m8n8.x4.shared.b16 {%0,%1,%2,%3},[%4];" \
                 : "=r"(r0), "=r"(r1), "=r"(r2), "=r"(r3) : "r"(addr))
#define CP16(sm, gp) \
    asm volatile("cp.async.cg.shared.global [%0], [%1], 16;" :: "r"(sm), "l"(gp))
#define CP_COMMIT() asm volatile("cp.async.commit_group;")
#define CP_WAIT1()  asm volatile("cp.async.wait_group 1;")
#define CP_WAIT0()  asm volatile("cp.async.wait_group 0;")

// ---------------------------------------------------------------------------
// Kernel 0: W2[k][n] (256x768 f32) -> g_w2t[n'][k] half, n' = (n%3)*256 + n/3
// ---------------------------------------------------------------------------
__global__ void __launch_bounds__(256) k0_w2half(const float* __restrict__ W2)
{
    const int idx = blockIdx.x * 256 + threadIdx.x;  // k*768 + n
    const int k = idx / 768;
    const int n = idx % 768;
    const int np = (n % 3) * 256 + n / 3;
    g_w2t[(size_t)np * 256 + k] = __float2half(W2[idx]);
}

// ---------------------------------------------------------------------------
// Kernel 1: fused patch-extract + (x @ W1) + bidirectional SRU scan (k=4)
// ---------------------------------------------------------------------------
__global__ void __launch_bounds__(128) k1_scan1(
    const float* __restrict__ x, const float* __restrict__ W1,
    const float* __restrict__ wc1, const float* __restrict__ b1)
{
    const int n1  = blockIdx.x;        // hp*8 + b
    const int dir = blockIdx.y;
    const int d   = threadIdx.x;       // 0..127 (output channel)
    const int lid = d & 31;
    const int hp  = n1 >> 3;
    const int b   = n1 & 7;

    u64t w01[FIN], w23[FIN];
    const int col0 = (dir * D + d) * 4;
#pragma unroll
    for (int f = 0; f < FIN; f++) {
        const float* wr = W1 + f * 1024 + col0;
        w01[f] = pack2(wr[0], wr[1]);
        w23[f] = pack2(wr[2], wr[3]);
    }
    const int chg = dir * D + d;
    const float vf = wc1[chg];
    const float vr = wc1[256 + chg];
    const float bf = b1[chg];
    const float br = b1[256 + chg];

    const int l0 = dir ? (L - 1) : 0;
    const int dl = dir ? -1 : 1;

    int xrowbase = 0, xww = 0;
    float nv = 0.0f;
    if (lid < FIN) {
        int c  = lid >> 2;
        int wh = (lid >> 1) & 1;
        xww    = lid & 1;
        xrowbase = ((b * 3 + c) * IMG + 2 * hp + wh) * IMG;
        nv = x[xrowbase + 2 * l0 + xww];
    }

    size_t oidx = ((size_t)hp * NSEQ + l0 * 8 + b) * 256 + chg;
    const ptrdiff_t ostep = (ptrdiff_t)dl * 8 * 256;

    float cst = 0.0f;
    for (int s = 0; s < L; s++) {
        const float cv = nv;
        if (lid < FIN && (s + 1) < L) {
            nv = x[xrowbase + 2 * (l0 + dl * (s + 1)) + xww];
        }
        u64t acc01 = 0ull, acc23 = 0ull;
#pragma unroll
        for (int f = 0; f < FIN; f++) {
            const float p = __shfl_sync(0xffffffffu, cv, f);
            const u64t pp = pack2(p, p);
            acc01 = fma2(pp, w01[f], acc01);
            acc23 = fma2(pp, w23[f], acc23);
        }
        float u0, u1, u2, u3;
        unpack2(acc01, u0, u1);
        unpack2(acc23, u2, u3);
        const float fg = sigmoidf_(u1 + vf * cst + bf);
        cst = fg * (cst - u0) + u0;
        const float rg = sigmoidf_(u2 + vr * cst + br);
        const float h  = rg * (cst - u3) + u3;
        g_a2h[oidx] = __float2half(h);
        oidx += ostep;
    }
}

// ---------------------------------------------------------------------------
// Kernel 2: fp16 GEMM  U2[100352,768] = a2h @ w2t^T
// BM=128, BN=128, BK=32; 256 threads; warp tile 32x64; ldmatrix + m16n8k16.
// cp.async 3-stage pipeline (dynamic smem, 60KB).
// ---------------------------------------------------------------------------
#define SAH 40                      // halves per smem row (80B, LDSM conflict-free)
#define STGB (128 * SAH * 2)        // bytes per stage per matrix (10240)
__global__ void __launch_bounds__(256, 2) k2_gemm_f16()
{
    extern __shared__ char k2smem[];
    __half* As = (__half*)k2smem;                 // 3 stages
    __half* Bs = (__half*)(k2smem + 3 * STGB);    // 3 stages

    const int tid  = threadIdx.x;
    const int lane = tid & 31;
    const int gid  = lane >> 2;     // 0..7
    const int tig  = lane & 3;      // 0..3
    const int warp = tid >> 5;
    const int wm   = (warp & 3) * 32;   // warp m offset
    const int wn   = (warp >> 2) * 64;  // warp n offset
    const int n0   = blockIdx.x * 128;
    const int m0   = blockIdx.y * 128;

    const int row = tid >> 1;           // 0..127
    const int kc  = (tid & 1) * 16;     // half-offset within 32-wide ktile

    const __half* Ag = g_a2h + (size_t)(m0 + row) * 256 + kc;
    const __half* Bg = g_w2t + (size_t)(n0 + row) * 256 + kc;

    const unsigned sa = (unsigned)__cvta_generic_to_shared(As + row * SAH + kc);
    const unsigned sb = (unsigned)__cvta_generic_to_shared(Bs + row * SAH + kc);

    // ldmatrix base addresses (stage 0, kk = 0)
    const unsigned aAddr = (unsigned)__cvta_generic_to_shared(As)
        + (((wm + (lane & 7) + (lane & 8)) * SAH + ((lane & 16) ? 8 : 0)) * 2);
    const unsigned bAddr = (unsigned)__cvta_generic_to_shared(Bs)
        + (((wn + (lane & 7) + ((lane & 16) ? 8 : 0)) * SAH + ((lane & 8) ? 8 : 0)) * 2);

    // prologue: stages 0,1 (ktiles 0,1)
#pragma unroll
    for (int s = 0; s < 2; s++) {
        CP16(sa + s * STGB,      Ag + s * 32);
        CP16(sa + s * STGB + 16, Ag + s * 32 + 8);
        CP16(sb + s * STGB,      Bg + s * 32);
        CP16(sb + s * STGB + 16, Bg + s * 32 + 8);
        CP_COMMIT();
    }

    float c[2][8][4];
#pragma unroll
    for (int mi = 0; mi < 2; mi++)
#pragma unroll
        for (int ni = 0; ni < 8; ni++)
#pragma unroll
            for (int j = 0; j < 4; j++) c[mi][ni][j] = 0.f;

    for (int kt = 0; kt < 8; kt++) {
        if (kt == 7) { CP_WAIT0(); } else { CP_WAIT1(); }
        __syncthreads();

        if (kt < 6) {
            const int s  = (kt + 2) % 3;
            const int k0 = (kt + 2) * 32;
            CP16(sa + s * STGB,      Ag + k0);
            CP16(sa + s * STGB + 16, Ag + k0 + 8);
            CP16(sb + s * STGB,      Bg + k0);
            CP16(sb + s * STGB + 16, Bg + k0 + 8);
            CP_COMMIT();
        }

        const unsigned aB = aAddr + (kt % 3) * STGB;
        const unsigned bB = bAddr + (kt % 3) * STGB;
#pragma unroll
        for (int kk = 0; kk < 32; kk += 16) {
            unsigned a[2][4];
#pragma unroll
            for (int mi = 0; mi < 2; mi++)
                LDSM4(a[mi][0], a[mi][1], a[mi][2], a[mi][3],
                      aB + mi * (16 * SAH * 2) + kk * 2);
#pragma unroll
            for (int nt = 0; nt < 4; nt++) {
                unsigned b00, b01, b10, b11;
                LDSM4(b00, b01, b10, b11, bB + nt * (16 * SAH * 2) + kk * 2);
#pragma unroll
                for (int mi = 0; mi < 2; mi++) {
                    asm volatile(
                        "mma.sync.aligned.m16n8k16.row.col.f32.f16.f16.f32 "
                        "{%0,%1,%2,%3}, {%4,%5,%6,%7}, {%8,%9}, {%0,%1,%2,%3};"
                        : "+f"(c[mi][2 * nt][0]), "+f"(c[mi][2 * nt][1]),
                          "+f"(c[mi][2 * nt][2]), "+f"(c[mi][2 * nt][3])
                        : "r"(a[mi][0]), "r"(a[mi][1]), "r"(a[mi][2]), "r"(a[mi][3]),
                          "r"(b00), "r"(b01));
                    asm volatile(
                        "mma.sync.aligned.m16n8k16.row.col.f32.f16.f16.f32 "
                        "{%0,%1,%2,%3}, {%4,%5,%6,%7}, {%8,%9}, {%0,%1,%2,%3};"
                        : "+f"(c[mi][2 * nt + 1][0]), "+f"(c[mi][2 * nt + 1][1]),
                          "+f"(c[mi][2 * nt + 1][2]), "+f"(c[mi][2 * nt + 1][3])
                        : "r"(a[mi][0]), "r"(a[mi][1]), "r"(a[mi][2]), "r"(a[mi][3]),
                          "r"(b10), "r"(b11));
                }
            }
        }
    }

#pragma unroll
    for (int mi = 0; mi < 2; mi++) {
#pragma unroll
        for (int ni = 0; ni < 8; ni++) {
            const int r0  = m0 + wm + mi * 16 + gid;
            const int col = n0 + wn + ni * 8 + tig * 2;
            *(__half2*)(g_u2h + (size_t)r0 * 768 + col) =
                __floats2half2_rn(c[mi][ni][0], c[mi][ni][1]);
            *(__half2*)(g_u2h + (size_t)(r0 + 8) * 768 + col) =
                __floats2half2_rn(c[mi][ni][2], c[mi][ni][3]);
        }
    }
}

// ---------------------------------------------------------------------------
// Kernel 3: bidirectional SRU scan (k=3) + coalesced output, sw-pipelined,
// half2 channel-pairs. Block 128 = 16 wp x 8 ch-pairs. Grid (7, 8, b*2+dir).
// ---------------------------------------------------------------------------
__global__ void __launch_bounds__(128) k3_scan2(
    const float* __restrict__ wc2, const float* __restrict__ b2,
    float* __restrict__ out)
{
    const int tid = threadIdx.x;
    const int tcp = tid & 7;           // ch-pair within group
    const int tw  = tid >> 3;          // wp within group (0..15)
    const int bz  = blockIdx.z;
    const int b   = bz >> 1;
    const int dir = bz & 1;
    const int wp  = blockIdx.x * 16 + tw;
    const int cg  = blockIdx.y * 16 + tcp * 2;     // even channel index
    const int ch  = dir * D + cg;
    const int n2  = wp * 8 + b;

    const float2 vf = *(const float2*)(wc2 + ch);
    const float2 vr = *(const float2*)(wc2 + 256 + ch);
    const float2 bf = *(const float2*)(b2 + ch);
    const float2 br = *(const float2*)(b2 + 256 + ch);
    const float SC = 1.41421356237309515f;

    const int l0 = dir ? (L - 1) : 0;
    const int dl = dir ? -1 : 1;

    __shared__ float hs[8][16][17];

    const int ow = tid & 15;
    const int oc = tid >> 4;   // 0..7 (handles oc and oc+8)
    float* ob0 = out + ((size_t)(b * 256 + dir * D + blockIdx.y * 16 + oc) * HP) * HP
                     + blockIdx.x * 16 + ow;
    float* ob1 = out + ((size_t)(b * 256 + dir * D + blockIdx.y * 16 + oc + 8) * HP) * HP
                     + blockIdx.x * 16 + ow;

    const ptrdiff_t ustep = (ptrdiff_t)dl * (NSEQ * 768 / 2);   // half2 units
    const ptrdiff_t astep = (ptrdiff_t)dl * (NSEQ * 256 / 2);
    const __half2* ub = (const __half2*)(g_u2h + ((size_t)l0 * NSEQ + n2) * 768 + ch);
    const __half2* ab = (const __half2*)(g_a2h + ((size_t)l0 * NSEQ + n2) * 256 + ch);

    __half2 cu0[8], cu1[8], cu2[8], cxp[8];
    __half2 pu0[8], pu1[8], pu2[8], pxp[8];

#pragma unroll
    for (int j = 0; j < 8; j++) {
        const __half2* up = ub + (ptrdiff_t)j * ustep;
        cu0[j] = up[0];
        cu1[j] = up[128];
        cu2[j] = up[256];
        cxp[j] = ab[(ptrdiff_t)j * astep];
    }

    float2 cst = make_float2(0.f, 0.f);
#pragma unroll 2
    for (int g = 0; g < 14; g++) {
        if (g < 13) {
#pragma unroll
            for (int j = 0; j < 8; j++) {
                const int s = (g + 1) * 8 + j;
                const __half2* up = ub + (ptrdiff_t)s * ustep;
                pu0[j] = up[0];
                pu1[j] = up[128];
                pu2[j] = up[256];
                pxp[j] = ab[(ptrdiff_t)s * astep];
            }
        }
#pragma unroll
        for (int j = 0; j < 8; j++) {
            const float2 u0  = __half22float2(cu0[j]);
            const float2 u1  = __half22float2(cu1[j]);
            const float2 u2v = __half22float2(cu2[j]);
            const float2 xp  = __half22float2(cxp[j]);
            const float fg0 = sigmoidf_(u1.x + vf.x * cst.x + bf.x);
            const float fg1 = sigmoidf_(u1.y + vf.y * cst.y + bf.y);
            cst.x = fg0 * (cst.x - u0.x) + u0.x;
            cst.y = fg1 * (cst.y - u0.y) + u0.y;
            const float rg0 = sigmoidf_(u2v.x + vr.x * cst.x + br.x);
            const float rg1 = sigmoidf_(u2v.y + vr.y * cst.y + br.y);
            const float x0 = xp.x * SC, x1 = xp.y * SC;
            hs[j][tcp * 2][tw]     = rg0 * (cst.x - x0) + x0;
            hs[j][tcp * 2 + 1][tw] = rg1 * (cst.y - x1) + x1;
        }
        __syncthreads();
#pragma unroll
        for (int j = 0; j < 8; j++) {
            const int l = l0 + dl * (g * 8 + j);
            ob0[(size_t)l * HP] = hs[j][oc][ow];
            ob1[(size_t)l * HP] = hs[j][oc + 8][ow];
        }
        __syncthreads();
#pragma unroll
        for (int j = 0; j < 8; j++) {
            cu0[j] = pu0[j];
            cu1[j] = pu1[j];
            cu2[j] = pu2[j];
            cxp[j] = pxp[j];
        }
    }
}

// ---------------------------------------------------------------------------
extern "C" void kernel_launch(void* const* d_in, const int* in_sizes, int n_in,
                              void* d_out, int out_size)
{
    const float* x   = (const float*)d_in[0];
    const float* W1  = (const float*)d_in[1];
    const float* wc1 = (const float*)d_in[2];
    const float* b1  = (const float*)d_in[3];
    const float* W2  = (const float*)d_in[4];
    const float* wc2 = (const float*)d_in[5];
    const float* b2  = (const float*)d_in[6];
    float* out = (float*)d_out;

    cudaFuncSetAttribute(k2_gemm_f16, cudaFuncAttributeMaxDynamicSharedMemorySize,
                         6 * STGB);

    k0_w2half<<<768, 256>>>(W2);
    k1_scan1<<<dim3(NSEQ, 2), 128>>>(x, W1, wc1, b1);
    k2_gemm_f16<<<dim3(768 / 128, M_TOT / 128), 256, 6 * STGB>>>();
    k3_scan2<<<dim3(HP / 16, 128 / 16, 16), 128>>>(wc2, b2, out);
}